// round 2
// baseline (speedup 1.0000x reference)
#include <cuda_runtime.h>
#include <float.h>
#include <math.h>

// Problem constants (fixed by the dataset)
#define BSZ      64
#define NH       32
#define KVH      8
#define GROUPS   4          // NH / KVH
#define HD       128
#define BS       16         // paged block size
#define BPS      128        // blocks per sequence
#define MAX_CTX  2048

// Split-KV config
#define CHUNK    256
#define NCHUNK   (MAX_CTX / CHUNK)   // 8
#define NTHREADS 256
#define NWARPS   (NTHREADS / 32)     // 8

#define SCALE 0.08838834764831845f   // 1/sqrt(128)

// Scratch for split-KV partials (static device globals: allocation-free)
__device__ float g_pout[(size_t)BSZ * KVH * NCHUNK * GROUPS * HD]; // 8 MB
__device__ float g_pm[BSZ * KVH * NCHUNK * GROUPS];
__device__ float g_pl[BSZ * KVH * NCHUNK * GROUPS];

__global__ __launch_bounds__(NTHREADS)
void attn_chunk_kernel(const float* __restrict__ q,
                       const float* __restrict__ kc,
                       const float* __restrict__ vc,
                       const int*   __restrict__ bt,
                       const int*   __restrict__ lens)
{
    const int bid   = blockIdx.x;
    const int chunk = bid % NCHUNK;
    const int kvh   = (bid / NCHUNK) % KVH;
    const int seq   = bid / (NCHUNK * KVH);
    const int tid   = threadIdx.x;
    const int warp  = tid >> 5;
    const int lane  = tid & 31;

    const int len    = lens[seq];
    const int cstart = chunk * CHUNK;
    if (cstart >= len) return;                 // inactive chunk: reduce never reads it
    const int tend   = min(CHUNK, len - cstart);

    const int sk    = seq * KVH + kvh;
    const int pbase = (sk * NCHUNK + chunk) * GROUPS;

    // Cache this chunk's block ids (kills the dependent bt->K load chain)
    __shared__ int s_blk[CHUNK / BS];          // 16 ints
    if (tid < CHUNK / BS)
        s_blk[tid] = bt[seq * BPS + (cstart >> 4) + tid];

    // Per-warp combine scratch
    __shared__ float s_red[NWARPS][GROUPS * HD];   // 16 KB
    __shared__ float s_m[NWARPS][GROUPS];
    __shared__ float s_l[NWARPS][GROUPS];
    __syncthreads();

    // Lane layout: g = lane&3, dims [(lane>>2)*16, +16).
    // 4 lanes share each K/V 16-dim slice (dedup'd in L1); score reduce = 3 shuffles;
    // PV accumulation needs no shuffles (lane output slice == lane V slice).
    const int g  = lane & 3;
    const int d0 = (lane >> 2) * 16;

    // Pre-scaled Q (folds the 1/sqrt(d) into Q once)
    const float* qp = q + ((size_t)(seq * NH + kvh * GROUPS + g)) * HD + d0;
    float qr[16];
    {
        const float4 a = *(const float4*)(qp + 0);
        const float4 b = *(const float4*)(qp + 4);
        const float4 c = *(const float4*)(qp + 8);
        const float4 d = *(const float4*)(qp + 12);
        qr[0]=a.x*SCALE; qr[1]=a.y*SCALE; qr[2]=a.z*SCALE; qr[3]=a.w*SCALE;
        qr[4]=b.x*SCALE; qr[5]=b.y*SCALE; qr[6]=b.z*SCALE; qr[7]=b.w*SCALE;
        qr[8]=c.x*SCALE; qr[9]=c.y*SCALE; qr[10]=c.z*SCALE; qr[11]=c.w*SCALE;
        qr[12]=d.x*SCALE; qr[13]=d.y*SCALE; qr[14]=d.z*SCALE; qr[15]=d.w*SCALE;
    }

    const size_t blk_stride = (size_t)KVH * BS * HD;     // floats per paged block
    const float* kbase = kc + (size_t)kvh * BS * HD + d0;
    const float* vbase = vc + (size_t)kvh * BS * HD + d0;

    float m = -FLT_MAX, l = 0.0f;
    float acc[16];
    #pragma unroll
    for (int i = 0; i < 16; ++i) acc[i] = 0.0f;

    for (int t = warp; t < tend; t += NWARPS) {
        const size_t off = (size_t)s_blk[t >> 4] * blk_stride + (size_t)(t & 15) * HD;

        // Issue all 8 independent 128-bit loads up front (K + V interleaved)
        const float4 k0 = *(const float4*)(kbase + off + 0);
        const float4 k1 = *(const float4*)(kbase + off + 4);
        const float4 k2 = *(const float4*)(kbase + off + 8);
        const float4 k3 = *(const float4*)(kbase + off + 12);
        const float4 v0 = *(const float4*)(vbase + off + 0);
        const float4 v1 = *(const float4*)(vbase + off + 4);
        const float4 v2 = *(const float4*)(vbase + off + 8);
        const float4 v3 = *(const float4*)(vbase + off + 12);

        float s = qr[0]*k0.x + qr[1]*k0.y + qr[2]*k0.z + qr[3]*k0.w
                + qr[4]*k1.x + qr[5]*k1.y + qr[6]*k1.z + qr[7]*k1.w
                + qr[8]*k2.x + qr[9]*k2.y + qr[10]*k2.z + qr[11]*k2.w
                + qr[12]*k3.x + qr[13]*k3.y + qr[14]*k3.z + qr[15]*k3.w;
        // reduce across the 8 dim-slices (xor by 4/8/16 preserves lane&3)
        s += __shfl_xor_sync(0xffffffffu, s, 4);
        s += __shfl_xor_sync(0xffffffffu, s, 8);
        s += __shfl_xor_sync(0xffffffffu, s, 16);

        if (s > m) {                       // rare after warmup
            const float alpha = __expf(m - s);   // exp(-inf)=0 on first hit
            m = s;
            l *= alpha;
            #pragma unroll
            for (int i = 0; i < 16; ++i) acc[i] *= alpha;
        }
        const float p = __expf(s - m);
        l += p;
        acc[0]  += p * v0.x;  acc[1]  += p * v0.y;  acc[2]  += p * v0.z;  acc[3]  += p * v0.w;
        acc[4]  += p * v1.x;  acc[5]  += p * v1.y;  acc[6]  += p * v1.z;  acc[7]  += p * v1.w;
        acc[8]  += p * v2.x;  acc[9]  += p * v2.y;  acc[10] += p * v2.z;  acc[11] += p * v2.w;
        acc[12] += p * v3.x;  acc[13] += p * v3.y;  acc[14] += p * v3.z;  acc[15] += p * v3.w;
    }

    // Per-warp partials -> smem
    {
        float* dst = &s_red[warp][g * HD + d0];
        #pragma unroll
        for (int i = 0; i < 16; i += 4)
            *(float4*)(dst + i) = make_float4(acc[i], acc[i+1], acc[i+2], acc[i+3]);
        if (lane < GROUPS) {               // lanes 0..3 carry g==lane, d0==0
            s_m[warp][lane] = m;
            s_l[warp][lane] = l;
        }
    }
    __syncthreads();

    // In-CTA log-sum-exp combine across warps, write unnormalized partial
    for (int idx = tid; idx < GROUPS * HD; idx += NTHREADS) {
        const int gg = idx >> 7;           // idx / HD
        float M = -FLT_MAX;
        #pragma unroll
        for (int w = 0; w < NWARPS; ++w) M = fmaxf(M, s_m[w][gg]);
        float L = 0.0f, o = 0.0f;
        #pragma unroll
        for (int w = 0; w < NWARPS; ++w) {
            const float f = __expf(s_m[w][gg] - M);   // empty warp: exp(-inf)=0
            L += s_l[w][gg] * f;
            o += s_red[w][idx] * f;
        }
        g_pout[(size_t)pbase * HD + idx] = o;
        if ((idx & (HD - 1)) == 0) {
            g_pm[pbase + gg] = M;
            g_pl[pbase + gg] = L;
        }
    }
}

// Combine split-KV partials with global log-sum-exp and normalize.
__global__ __launch_bounds__(GROUPS * HD)
void attn_reduce_kernel(float* __restrict__ out, const int* __restrict__ lens)
{
    const int sk  = blockIdx.x;            // seq*KVH + kvh
    const int seq = sk / KVH;
    const int kvh = sk % KVH;
    const int g   = threadIdx.x / HD;
    const int d   = threadIdx.x % HD;

    const int nact = (lens[seq] + CHUNK - 1) / CHUNK;   // only active chunks written

    float M = -FLT_MAX;
    for (int c = 0; c < nact; ++c)
        M = fmaxf(M, g_pm[(sk * NCHUNK + c) * GROUPS + g]);

    float L = 0.0f, o = 0.0f;
    for (int c = 0; c < nact; ++c) {
        const int   pidx = (sk * NCHUNK + c) * GROUPS + g;
        const float f    = __expf(g_pm[pidx] - M);
        L += g_pl[pidx] * f;
        o += g_pout[(size_t)pidx * HD + d] * f;
    }
    out[(size_t)seq * (NH * HD) + (kvh * GROUPS + g) * HD + d] = o / L;
}

extern "C" void kernel_launch(void* const* d_in, const int* in_sizes, int n_in,
                              void* d_out, int out_size)
{
    const float* q    = (const float*)d_in[0];
    const float* kc   = (const float*)d_in[1];
    const float* vc   = (const float*)d_in[2];
    const int*   bt   = (const int*)d_in[3];
    const int*   lens = (const int*)d_in[4];
    float* out = (float*)d_out;

    attn_chunk_kernel<<<BSZ * KVH * NCHUNK, NTHREADS>>>(q, kc, vc, bt, lens);
    attn_reduce_kernel<<<BSZ * KVH, GROUPS * HD>>>(out, lens);
}

// round 3
// speedup vs baseline: 1.3736x; 1.3736x over previous
#include <cuda_runtime.h>
#include <float.h>
#include <math.h>

// Problem constants (fixed by the dataset)
#define BSZ      64
#define NH       32
#define KVH      8
#define GROUPS   4          // NH / KVH
#define HD       128
#define BS       16         // paged block size
#define BPS      128        // blocks per sequence
#define MAX_CTX  2048

// Split-KV config
#define CHUNK    256
#define NCHUNK   (MAX_CTX / CHUNK)   // 8
#define NTHREADS 256
#define NWARPS   (NTHREADS / 32)     // 8

#define SCALE 0.08838834764831845f   // 1/sqrt(128)

// Scratch for split-KV partials (static device globals: allocation-free)
__device__ float g_pout[(size_t)BSZ * KVH * NCHUNK * GROUPS * HD]; // 8 MB
__device__ float g_pm[BSZ * KVH * NCHUNK * GROUPS];
__device__ float g_pl[BSZ * KVH * NCHUNK * GROUPS];

__global__ __launch_bounds__(NTHREADS)
void attn_chunk_kernel(const float* __restrict__ q,
                       const float* __restrict__ kc,
                       const float* __restrict__ vc,
                       const int*   __restrict__ bt,
                       const int*   __restrict__ lens)
{
    const int bid   = blockIdx.x;
    const int chunk = bid % NCHUNK;
    const int kvh   = (bid / NCHUNK) % KVH;
    const int seq   = bid / (NCHUNK * KVH);
    const int tid   = threadIdx.x;
    const int warp  = tid >> 5;
    const int lane  = tid & 31;

    const int len    = lens[seq];
    const int cstart = chunk * CHUNK;
    if (cstart >= len) return;                 // inactive: reduce kernel won't read it
    const int tend   = min(CHUNK, len - cstart);

    const int sk    = seq * KVH + kvh;
    const int pbase = (sk * NCHUNK + chunk) * GROUPS;

    __shared__ int   s_blk[CHUNK / BS];            // 16 ints
    __shared__ float s_sc[GROUPS][CHUNK];          // scores -> probs (4 KB)
    __shared__ float s_red[NWARPS][GROUPS * HD];   // PV cross-warp reduce (16 KB)

    if (tid < CHUNK / BS)
        s_blk[tid] = bt[seq * BPS + (cstart >> 4) + tid];
    __syncthreads();

    const size_t blk_stride = (size_t)KVH * BS * HD;     // floats per paged block
    const float* kbase = kc + (size_t)kvh * BS * HD;
    const float* vbase = vc + (size_t)kvh * BS * HD;

    // ---------------- Phase 1: scores (coalesced K, 6-shuffle 4-head reduce) ----
    // Lane l loads K[token][4l..4l+4] (one LDG.128 = 4 lines = 4 wavefronts).
    // Each lane computes 4 per-head partials; reduce-scatter (xor1,xor1,xor2)
    // lands head g in lanes with lane&3==g, then xor4/8/16 finish the sum.
    {
        // Per-lane Q slices for all 4 heads, pre-scaled
        float4 qh[GROUPS];
        #pragma unroll
        for (int g = 0; g < GROUPS; ++g) {
            float4 t = *(const float4*)(q + ((size_t)(seq * NH + kvh * GROUPS + g)) * HD + lane * 4);
            qh[g] = make_float4(t.x * SCALE, t.y * SCALE, t.z * SCALE, t.w * SCALE);
        }
        const int bit0 = lane & 1;
        const int bit1 = lane & 2;

        const int t0 = warp * (CHUNK / NWARPS);
        const int t1 = t0 + (CHUNK / NWARPS);
        #pragma unroll 4
        for (int t = t0; t < t1; ++t) {
            float val = -FLT_MAX;
            if (t < tend) {               // uniform across warp
                const size_t off = (size_t)s_blk[t >> 4] * blk_stride + (size_t)(t & 15) * HD;
                const float4 k4 = *(const float4*)(kbase + off + lane * 4);

                float p0 = qh[0].x*k4.x + qh[0].y*k4.y + qh[0].z*k4.z + qh[0].w*k4.w;
                float p1 = qh[1].x*k4.x + qh[1].y*k4.y + qh[1].z*k4.z + qh[1].w*k4.w;
                float p2 = qh[2].x*k4.x + qh[2].y*k4.y + qh[2].z*k4.z + qh[2].w*k4.w;
                float p3 = qh[3].x*k4.x + qh[3].y*k4.y + qh[3].z*k4.z + qh[3].w*k4.w;

                // reduce-scatter across lane quads
                float rA = __shfl_xor_sync(0xffffffffu, bit0 ? p0 : p1, 1);
                float x  = (bit0 ? p1 : p0) + rA;            // head bit0, pair-sum
                float rB = __shfl_xor_sync(0xffffffffu, bit0 ? p2 : p3, 1);
                float y  = (bit0 ? p3 : p2) + rB;            // head 2+bit0, pair-sum
                float rC = __shfl_xor_sync(0xffffffffu, bit1 ? x : y, 2);
                float s  = (bit1 ? y : x) + rC;              // head lane&3, quad-sum
                // finish across quads (preserves lane&3)
                s += __shfl_xor_sync(0xffffffffu, s, 4);
                s += __shfl_xor_sync(0xffffffffu, s, 8);
                s += __shfl_xor_sync(0xffffffffu, s, 16);
                val = s;
            }
            if (lane < GROUPS) s_sc[lane][t] = val;   // lane g holds head g
        }
    }
    __syncthreads();

    // ---------------- Phase 2: chunk-local softmax (m, l, probs) -------
    if (warp < GROUPS) {
        const int g = warp;
        float m = -FLT_MAX;
        #pragma unroll
        for (int t = lane; t < CHUNK; t += 32) m = fmaxf(m, s_sc[g][t]);
        #pragma unroll
        for (int off = 16; off > 0; off >>= 1)
            m = fmaxf(m, __shfl_xor_sync(0xffffffffu, m, off));

        float l = 0.0f;
        #pragma unroll
        for (int t = lane; t < CHUNK; t += 32) {
            const float s = s_sc[g][t];
            const float p = (s > -0.5f * FLT_MAX) ? __expf(s - m) : 0.0f;
            s_sc[g][t] = p;
            l += p;
        }
        #pragma unroll
        for (int off = 16; off > 0; off >>= 1)
            l += __shfl_xor_sync(0xffffffffu, l, off);

        if (lane == 0) {
            g_pm[pbase + g] = m;
            g_pl[pbase + g] = l;
        }
    }
    __syncthreads();

    // ---------------- Phase 3: O_partial = P . V (coalesced) -----------
    {
        const int d4 = lane;               // float4 column: bytes 16*lane
        float acc[GROUPS][4];
        #pragma unroll
        for (int g = 0; g < GROUPS; ++g) {
            acc[g][0] = 0.f; acc[g][1] = 0.f; acc[g][2] = 0.f; acc[g][3] = 0.f;
        }

        #pragma unroll 2
        for (int t = warp; t < tend; t += NWARPS) {
            const size_t off = (size_t)s_blk[t >> 4] * blk_stride + (size_t)(t & 15) * HD;
            const float4 v4 = *(const float4*)(vbase + off + d4 * 4);
            #pragma unroll
            for (int g = 0; g < GROUPS; ++g) {
                const float p = s_sc[g][t];
                acc[g][0] += p * v4.x;
                acc[g][1] += p * v4.y;
                acc[g][2] += p * v4.z;
                acc[g][3] += p * v4.w;
            }
        }

        #pragma unroll
        for (int g = 0; g < GROUPS; ++g) {
            float4* r = (float4*)&s_red[warp][g * HD + d4 * 4];
            *r = make_float4(acc[g][0], acc[g][1], acc[g][2], acc[g][3]);
        }
    }
    __syncthreads();

    // Cross-warp reduce + write unnormalized partial output
    for (int idx = tid; idx < GROUPS * HD; idx += NTHREADS) {
        float s = 0.0f;
        #pragma unroll
        for (int w = 0; w < NWARPS; ++w) s += s_red[w][idx];
        g_pout[(size_t)pbase * HD + idx] = s;
    }
}

// Combine split-KV partials with global log-sum-exp and normalize.
__global__ __launch_bounds__(GROUPS * HD)
void attn_reduce_kernel(float* __restrict__ out, const int* __restrict__ lens)
{
    const int sk  = blockIdx.x;            // seq*KVH + kvh
    const int seq = sk / KVH;
    const int kvh = sk % KVH;
    const int g   = threadIdx.x / HD;
    const int d   = threadIdx.x % HD;

    const int nact = (lens[seq] + CHUNK - 1) / CHUNK;   // only active chunks written

    float M = -FLT_MAX;
    for (int c = 0; c < nact; ++c)
        M = fmaxf(M, g_pm[(sk * NCHUNK + c) * GROUPS + g]);

    float L = 0.0f, o = 0.0f;
    for (int c = 0; c < nact; ++c) {
        const int   pidx = (sk * NCHUNK + c) * GROUPS + g;
        const float f    = __expf(g_pm[pidx] - M);
        L += g_pl[pidx] * f;
        o += g_pout[(size_t)pidx * HD + d] * f;
    }
    out[(size_t)seq * (NH * HD) + (kvh * GROUPS + g) * HD + d] = o / L;
}

extern "C" void kernel_launch(void* const* d_in, const int* in_sizes, int n_in,
                              void* d_out, int out_size)
{
    const float* q    = (const float*)d_in[0];
    const float* kc   = (const float*)d_in[1];
    const float* vc   = (const float*)d_in[2];
    const int*   bt   = (const int*)d_in[3];
    const int*   lens = (const int*)d_in[4];
    float* out = (float*)d_out;

    attn_chunk_kernel<<<BSZ * KVH * NCHUNK, NTHREADS>>>(q, kc, vc, bt, lens);
    attn_reduce_kernel<<<BSZ * KVH, GROUPS * HD>>>(out, lens);
}